// round 16
// baseline (speedup 1.0000x reference)
#include <cuda_runtime.h>
#include <cuda_bf16.h>
#include <cstdint>

#define N_NODES 100000
#define N_EDGES 1250000
#define IN_DIM  64
#define HID     128
#define OUT_DIM 64
#define SLOTS   96                       // fixed per-node bin capacity
#define BIN_BLOCKS  1221                 // ceil((N_EDGES/4)/256)
#define PREP_BLOCKS 224                  // ceil(57344/256)

typedef unsigned long long ull;

// ---------------- scratch ---------------------------------------------------
__device__ int    g_cnt [N_NODES];
__device__ __align__(16) int g_bcol[(size_t)N_NODES * SLOTS];   // 38.4 MB
// weight image: per layer [n][k] hi/lo bf16 planes, 256B rows, XOR swizzle
__device__ __align__(16) unsigned char g_wimg[229376];

// ---------------- helpers ---------------------------------------------------
__device__ __forceinline__ uint32_t smem_u32(const void* p) {
    uint32_t a;
    asm("{ .reg .u64 t; cvta.to.shared.u64 t, %1; cvt.u32.u64 %0, t; }" : "=r"(a) : "l"(p));
    return a;
}
__device__ __forceinline__ uint32_t phys(int row, int col) {
    return (uint32_t)row * 256u
         + (uint32_t)(((col >> 3) ^ (row & 7)) << 4)
         + (uint32_t)((col & 7) << 1);
}
__device__ __forceinline__ uint32_t bf2pack(float f0, float f1) {
    __nv_bfloat162 t = __floats2bfloat162_rn(f0, f1);
    return *reinterpret_cast<uint32_t*>(&t);
}
__device__ __forceinline__ void ldsm_x4(uint32_t* r, uint32_t addr) {
    asm volatile("ldmatrix.sync.aligned.m8n8.x4.shared.b16 {%0,%1,%2,%3}, [%4];"
                 : "=r"(r[0]), "=r"(r[1]), "=r"(r[2]), "=r"(r[3]) : "r"(addr));
}
__device__ __forceinline__ void mma_bf16(float* d, const uint32_t* a, uint32_t b0, uint32_t b1) {
    asm volatile(
        "mma.sync.aligned.m16n8k16.row.col.f32.bf16.bf16.f32 "
        "{%0,%1,%2,%3}, {%4,%5,%6,%7}, {%8,%9}, {%0,%1,%2,%3};"
        : "+f"(d[0]), "+f"(d[1]), "+f"(d[2]), "+f"(d[3])
        : "r"(a[0]), "r"(a[1]), "r"(a[2]), "r"(a[3]), "r"(b0), "r"(b1));
}
__device__ __forceinline__ void cp16(uint32_t dst, const void* src) {
    asm volatile("cp.async.cg.shared.global [%0], [%1], 16;" :: "r"(dst), "l"(src));
}
#define CP_COMMIT() asm volatile("cp.async.commit_group;" ::: "memory")
#define CP_WAIT0()  asm volatile("cp.async.wait_group 0;" ::: "memory")

// ================= bin + weight-prep (merged, independent work) ==============
__global__ void bin_prep_kernel(const int* __restrict__ ei,
                                const float* __restrict__ W1, const float* __restrict__ W2,
                                const float* __restrict__ W3, const float* __restrict__ W4) {
    int b = blockIdx.x;
    if (b < BIN_BLOCKS) {
        // --- slot binning: 4 edges per thread ---
        int t = b * 256 + threadIdx.x;
        int e0 = t * 4;
        if (e0 >= N_EDGES) return;
        int4 r = *reinterpret_cast<const int4*>(ei + e0);
        int4 c = *reinterpret_cast<const int4*>(ei + N_EDGES + e0);
        int p0 = atomicAdd(&g_cnt[r.x], 1);
        int p1 = atomicAdd(&g_cnt[r.y], 1);
        int p2 = atomicAdd(&g_cnt[r.z], 1);
        int p3 = atomicAdd(&g_cnt[r.w], 1);
        if (p0 < SLOTS) g_bcol[(size_t)r.x * SLOTS + p0] = c.x;
        if (p1 < SLOTS) g_bcol[(size_t)r.y * SLOTS + p1] = c.y;
        if (p2 < SLOTS) g_bcol[(size_t)r.z * SLOTS + p2] = c.z;
        if (p3 < SLOTS) g_bcol[(size_t)r.w * SLOTS + p3] = c.w;
    } else {
        // --- weight image prep ---
        int t = (b - BIN_BLOCKS) * 256 + threadIdx.x;
        if (t >= 57344) return;
        const float* W; int e, nout; uint32_t hoff, psz;
        if      (t < 16384) { e = t;         W = W1; nout = 128; hoff = 0;      psz = 32768; }
        else if (t < 32768) { e = t - 16384; W = W2; nout = 128; hoff = 65536;  psz = 32768; }
        else if (t < 49152) { e = t - 32768; W = W3; nout = 128; hoff = 131072; psz = 32768; }
        else                { e = t - 49152; W = W4; nout = 64;  hoff = 196608; psz = 16384; }
        int n = e >> 7;
        int k = e & 127;
        float w = W[k * nout + n];
        __nv_bfloat16 h = __float2bfloat16_rn(w);
        float res = w - __bfloat162float(h);
        __nv_bfloat16 l = __float2bfloat16_rn(res);
        uint32_t off = phys(n, k);
        *reinterpret_cast<__nv_bfloat16*>(g_wimg + hoff + off)       = h;
        *reinterpret_cast<__nv_bfloat16*>(g_wimg + hoff + psz + off) = l;
    }
}

// ---------------- fused gather + 4-layer MLP on HMMA ------------------------
#define SM_A_HI 0
#define SM_A_LO 16384
#define SM_W_HI 32768
#define SM_BIAS 98304
#define SM_TOTAL (98304 + 2048)     // 100352 bytes -> 2 CTAs/SM

template<int MT>
__device__ __forceinline__ void load_frags(
    uint32_t sb, uint32_t wlo, int kc,
    const uint32_t* arow_off, const int* ar7, int abit,
    const uint32_t* brow_off, const int* br7, int bbit,
    uint32_t ah[][4], uint32_t al[][4], uint32_t bh[][4], uint32_t bl[][4]) {
    #pragma unroll
    for (int mt = 0; mt < MT; mt++) {
        uint32_t off = arow_off[mt] + (uint32_t)((((kc << 1) + abit) ^ ar7[mt]) << 4);
        ldsm_x4(ah[mt], sb + SM_A_HI + off);
        ldsm_x4(al[mt], sb + SM_A_LO + off);
    }
    #pragma unroll
    for (int jp = 0; jp < 2; jp++) {
        uint32_t off = brow_off[jp] + (uint32_t)((((kc << 1) + bbit) ^ br7[jp]) << 4);
        ldsm_x4(bh[jp], sb + SM_W_HI + off);
        ldsm_x4(bl[jp], wlo + off);
    }
}

template<int NOUT, bool LAST>
__device__ __forceinline__ void layer_body(char* smem, uint32_t sb, float* __restrict__ out,
                                           int wid, int lane, int m0, const float* bl_s,
                                           uint32_t next_hoff, int next_f4, int tid) {
    constexpr int MT = (NOUT == 128) ? 2 : 1;
    const uint32_t wlo = sb + SM_W_HI + (uint32_t)NOUT * 256u;

    int warpM = (NOUT == 128) ? (wid >> 2) : (wid >> 1);
    int warpN = (NOUT == 128) ? (wid & 3) : (wid & 1);
    int mi    = lane >> 3;
    int lane8 = lane & 7;
    int g     = lane >> 2;
    int tt    = lane & 3;
    int nbase = warpN * 32;

    uint32_t arow_off[MT]; int ar7[MT]; int abit = mi >> 1;
    #pragma unroll
    for (int mt = 0; mt < MT; mt++) {
        int row = warpM * (MT * 16) + mt * 16 + (mi & 1) * 8 + lane8;
        arow_off[mt] = (uint32_t)row * 256u;
        ar7[mt] = row & 7;
    }
    uint32_t brow_off[2]; int br7[2]; int bbit = mi & 1;
    #pragma unroll
    for (int jp = 0; jp < 2; jp++) {
        int row = nbase + jp * 16 + (mi >> 1) * 8 + lane8;
        brow_off[jp] = (uint32_t)row * 256u;
        br7[jp] = row & 7;
    }

    float acc[MT][4][4];
    #pragma unroll
    for (int mt = 0; mt < MT; mt++)
        #pragma unroll
        for (int j = 0; j < 4; j++)
            #pragma unroll
            for (int q = 0; q < 4; q++) acc[mt][j][q] = 0.f;

    uint32_t ah[2][MT][4], al[2][MT][4], bh[2][2][4], bl[2][2][4];
    load_frags<MT>(sb, wlo, 0, arow_off, ar7, abit, brow_off, br7, bbit,
                   ah[0], al[0], bh[0], bl[0]);
    #pragma unroll
    for (int kc = 0; kc < 8; kc++) {
        int cur = kc & 1;
        if (kc < 7)
            load_frags<MT>(sb, wlo, kc + 1, arow_off, ar7, abit, brow_off, br7, bbit,
                           ah[cur ^ 1], al[cur ^ 1], bh[cur ^ 1], bl[cur ^ 1]);
        #pragma unroll
        for (int jp = 0; jp < 2; jp++)
            #pragma unroll
            for (int mt = 0; mt < MT; mt++) {
                mma_bf16(acc[mt][jp * 2],     ah[cur][mt], bh[cur][jp][0], bh[cur][jp][1]);
                mma_bf16(acc[mt][jp * 2 + 1], ah[cur][mt], bh[cur][jp][2], bh[cur][jp][3]);
            }
        #pragma unroll
        for (int jp = 0; jp < 2; jp++)
            #pragma unroll
            for (int mt = 0; mt < MT; mt++) {
                mma_bf16(acc[mt][jp * 2],     ah[cur][mt], bl[cur][jp][0], bl[cur][jp][1]);
                mma_bf16(acc[mt][jp * 2 + 1], ah[cur][mt], bl[cur][jp][2], bl[cur][jp][3]);
            }
        #pragma unroll
        for (int jp = 0; jp < 2; jp++)
            #pragma unroll
            for (int mt = 0; mt < MT; mt++) {
                mma_bf16(acc[mt][jp * 2],     al[cur][mt], bh[cur][jp][0], bh[cur][jp][1]);
                mma_bf16(acc[mt][jp * 2 + 1], al[cur][mt], bh[cur][jp][2], bh[cur][jp][3]);
            }
    }
    __syncthreads();

    if (!LAST) {
        const char* src = reinterpret_cast<const char*>(g_wimg + next_hoff);
        uint32_t dst = sb + SM_W_HI;
        for (int i = tid; i < next_f4; i += 256)
            cp16(dst + (uint32_t)i * 16u, src + (size_t)i * 16);
        CP_COMMIT();
    }

    #pragma unroll
    for (int mt = 0; mt < MT; mt++) {
        int rg0 = warpM * (MT * 16) + mt * 16 + g;
        #pragma unroll
        for (int j = 0; j < 4; j++) {
            int c0 = nbase + j * 8 + tt * 2;
            float bv0 = bl_s[c0], bv1 = bl_s[c0 + 1];
            float* d = acc[mt][j];
            if (!LAST) {
                float f0 = fmaxf(d[0] + bv0, 0.f), f1 = fmaxf(d[1] + bv1, 0.f);
                float f2 = fmaxf(d[2] + bv0, 0.f), f3 = fmaxf(d[3] + bv1, 0.f);
                __nv_bfloat16 h0 = __float2bfloat16_rn(f0), h1 = __float2bfloat16_rn(f1);
                __nv_bfloat16 h2 = __float2bfloat16_rn(f2), h3 = __float2bfloat16_rn(f3);
                uint32_t o0 = phys(rg0, c0);
                uint32_t o1 = phys(rg0 + 8, c0);
                *reinterpret_cast<uint32_t*>(smem + SM_A_HI + o0) =
                    bf2pack(__bfloat162float(h0), __bfloat162float(h1));
                *reinterpret_cast<uint32_t*>(smem + SM_A_LO + o0) =
                    bf2pack(f0 - __bfloat162float(h0), f1 - __bfloat162float(h1));
                *reinterpret_cast<uint32_t*>(smem + SM_A_HI + o1) =
                    bf2pack(__bfloat162float(h2), __bfloat162float(h3));
                *reinterpret_cast<uint32_t*>(smem + SM_A_LO + o1) =
                    bf2pack(f2 - __bfloat162float(h2), f3 - __bfloat162float(h3));
            } else {
                int node0 = m0 + rg0;
                int node1 = node0 + 8;
                if (node0 < N_NODES)
                    *reinterpret_cast<float2*>(out + (size_t)node0 * OUT_DIM + c0) =
                        make_float2(d[0] + bv0, d[1] + bv1);
                if (node1 < N_NODES)
                    *reinterpret_cast<float2*>(out + (size_t)node1 * OUT_DIM + c0) =
                        make_float2(d[2] + bv0, d[3] + bv1);
            }
        }
    }
    if (!LAST) CP_WAIT0();
    __syncthreads();
}

__global__ void __launch_bounds__(256, 2)
fused_mlp(const float* __restrict__ x,
          const float* __restrict__ b1, const float* __restrict__ b2,
          const float* __restrict__ b3, const float* __restrict__ b4,
          float* __restrict__ out) {
    extern __shared__ char smem[];
    uint32_t sb = smem_u32(smem);
    int tid = threadIdx.x, wid = tid >> 5, lane = tid & 31;
    int m0 = blockIdx.x * 64;

    float* bias_s = reinterpret_cast<float*>(smem + SM_BIAS);

    // layer-0 weights via cp.async, overlapping gather + A fill
    {
        const char* src = reinterpret_cast<const char*>(g_wimg);
        uint32_t dst = sb + SM_W_HI;
        for (int i = tid; i < 4096; i += 256)
            cp16(dst + (uint32_t)i * 16u, src + (size_t)i * 16);
        CP_COMMIT();
    }

    // ---- A fill with edge-split slot gather: 4 threads per row ----
    // thread sub = (edge parity, column half); shfl.xor(1) merges parity pairs.
    {
        int row  = tid >> 2;
        int sub  = tid & 3;
        int epar = sub & 1;            // which edges this thread walks
        int chal = sub >> 1;           // which half of the 16-float4 row
        int node = m0 + row;
        int cnt = 0;

        float4 a8[8];
        #pragma unroll
        for (int i = 0; i < 8; i++) a8[i] = make_float4(0.f, 0.f, 0.f, 0.f);

        if (node < N_NODES) {
            cnt = g_cnt[node];
            int lim = cnt < SLOTS ? cnt : SLOTS;
            const int* bc = g_bcol + (size_t)node * SLOTS;
            const float4* xb = reinterpret_cast<const float4*>(x);
            for (int e = epar; e < lim; e += 2) {
                int cn = bc[e];
                const float4* xr = xb + (size_t)cn * 16 + chal * 8;
                #pragma unroll
                for (int i = 0; i < 8; i++) {
                    float4 v = xr[i];
                    a8[i].x += v.x; a8[i].y += v.y; a8[i].z += v.z; a8[i].w += v.w;
                }
            }
        }
        // merge edge-parity partner (lane xor 1, same row)
        #pragma unroll
        for (int i = 0; i < 8; i++) {
            a8[i].x += __shfl_xor_sync(0xffffffffu, a8[i].x, 1);
            a8[i].y += __shfl_xor_sync(0xffffffffu, a8[i].y, 1);
            a8[i].z += __shfl_xor_sync(0xffffffffu, a8[i].z, 1);
            a8[i].w += __shfl_xor_sync(0xffffffffu, a8[i].w, 1);
        }
        float inv = 1.0f / (float)(cnt > 0 ? cnt : 1);
        float4 acc[4];
        #pragma unroll
        for (int j = 0; j < 4; j++) {
            float4 v = a8[4 * (sub & 1) + j];
            acc[j] = make_float4(v.x * inv, v.y * inv, v.z * inv, v.w * inv);
        }

        // x half: this thread's 4 float4 (cols sub*16 .. sub*16+15)
        int nsafe = node < N_NODES ? node : 0;
        const float4* xs = reinterpret_cast<const float4*>(x) + (size_t)nsafe * 16 + sub * 4;
        float4 xv[4];
        #pragma unroll
        for (int i = 0; i < 4; i++)
            xv[i] = (node < N_NODES) ? xs[i] : make_float4(0.f, 0.f, 0.f, 0.f);

        #pragma unroll
        for (int half = 0; half < 2; half++) {
            #pragma unroll
            for (int i = 0; i < 4; i++) {
                float4 v = half ? acc[i] : xv[i];
                if (half && node >= N_NODES) v = make_float4(0.f, 0.f, 0.f, 0.f);
                __nv_bfloat16 h0 = __float2bfloat16_rn(v.x), h1 = __float2bfloat16_rn(v.y);
                __nv_bfloat16 h2 = __float2bfloat16_rn(v.z), h3 = __float2bfloat16_rn(v.w);
                float r0 = v.x - __bfloat162float(h0), r1 = v.y - __bfloat162float(h1);
                float r2 = v.z - __bfloat162float(h2), r3 = v.w - __bfloat162float(h3);
                int c = half * 64 + (sub * 4 + i) * 4;
                uint32_t off = phys(row, c);
                ull hv = (ull)bf2pack(__bfloat162float(h0), __bfloat162float(h1))
                       | ((ull)bf2pack(__bfloat162float(h2), __bfloat162float(h3)) << 32);
                ull lv = (ull)bf2pack(r0, r1) | ((ull)bf2pack(r2, r3) << 32);
                *reinterpret_cast<ull*>(smem + SM_A_HI + off) = hv;
                *reinterpret_cast<ull*>(smem + SM_A_LO + off) = lv;
            }
        }
        if (tid < 128) {
            bias_s[tid]       = b1[tid];
            bias_s[128 + tid] = b2[tid];
            bias_s[256 + tid] = b3[tid];
            bias_s[384 + tid] = (tid < 64) ? b4[tid] : 0.f;
        }
    }
    CP_WAIT0();
    __syncthreads();

    layer_body<128, false>(smem, sb, out, wid, lane, m0, bias_s,       65536, 4096, tid);
    layer_body<128, false>(smem, sb, out, wid, lane, m0, bias_s + 128, 131072, 4096, tid);
    layer_body<128, false>(smem, sb, out, wid, lane, m0, bias_s + 256, 196608, 2048, tid);
    layer_body<64,  true >(smem, sb, out, wid, lane, m0, bias_s + 384, 0, 0, tid);
}

// ---------------- launch ----------------------------------------------------
extern "C" void kernel_launch(void* const* d_in, const int* in_sizes, int n_in,
                              void* d_out, int out_size) {
    const float* x  = (const float*)d_in[0];
    const int*   ei = (const int*)  d_in[1];
    const float* W1 = (const float*)d_in[2];
    const float* b1 = (const float*)d_in[3];
    const float* W2 = (const float*)d_in[4];
    const float* b2 = (const float*)d_in[5];
    const float* W3 = (const float*)d_in[6];
    const float* b3 = (const float*)d_in[7];
    const float* W4 = (const float*)d_in[8];
    const float* b4 = (const float*)d_in[9];
    float* out = (float*)d_out;

    cudaFuncSetAttribute(fused_mlp, cudaFuncAttributeMaxDynamicSharedMemorySize, SM_TOTAL);

    // zero per-node counters (graph-capturable async memset)
    void* cnt_ptr = nullptr;
    cudaGetSymbolAddress(&cnt_ptr, g_cnt);
    cudaMemsetAsync(cnt_ptr, 0, N_NODES * sizeof(int));

    // merged slot-binning + weight prep
    bin_prep_kernel<<<BIN_BLOCKS + PREP_BLOCKS, 256>>>(ei, W1, W2, W3, W4);
    // fused gather + 4-layer MLP
    int gblocks = (N_NODES + 63) / 64;   // 1563
    fused_mlp<<<gblocks, 256, SM_TOTAL>>>(x, b1, b2, b3, b4, out);
}

// round 17
// speedup vs baseline: 1.3100x; 1.3100x over previous
#include <cuda_runtime.h>
#include <cuda_bf16.h>
#include <cstdint>

#define N_NODES 100000
#define N_EDGES 1250000
#define IN_DIM  64
#define HID     128
#define OUT_DIM 64
#define SLOTS   96                       // fixed per-node bin capacity
#define BIN_BLOCKS  1221                 // ceil((N_EDGES/4)/256)
#define PREP_BLOCKS 224                  // ceil(57344/256)

typedef unsigned long long ull;

// ---------------- scratch ---------------------------------------------------
__device__ int    g_cnt [N_NODES];
__device__ __align__(16) int g_bcol[(size_t)N_NODES * SLOTS];   // 38.4 MB
// weight image: per layer [n][k] hi/lo bf16 planes, 256B rows, XOR swizzle
__device__ __align__(16) unsigned char g_wimg[229376];

// ---------------- helpers ---------------------------------------------------
__device__ __forceinline__ uint32_t smem_u32(const void* p) {
    uint32_t a;
    asm("{ .reg .u64 t; cvta.to.shared.u64 t, %1; cvt.u32.u64 %0, t; }" : "=r"(a) : "l"(p));
    return a;
}
__device__ __forceinline__ uint32_t phys(int row, int col) {
    return (uint32_t)row * 256u
         + (uint32_t)(((col >> 3) ^ (row & 7)) << 4)
         + (uint32_t)((col & 7) << 1);
}
__device__ __forceinline__ uint32_t bf2pack(float f0, float f1) {
    __nv_bfloat162 t = __floats2bfloat162_rn(f0, f1);
    return *reinterpret_cast<uint32_t*>(&t);
}
__device__ __forceinline__ void ldsm_x4(uint32_t* r, uint32_t addr) {
    asm volatile("ldmatrix.sync.aligned.m8n8.x4.shared.b16 {%0,%1,%2,%3}, [%4];"
                 : "=r"(r[0]), "=r"(r[1]), "=r"(r[2]), "=r"(r[3]) : "r"(addr));
}
__device__ __forceinline__ void mma_bf16(float* d, const uint32_t* a, uint32_t b0, uint32_t b1) {
    asm volatile(
        "mma.sync.aligned.m16n8k16.row.col.f32.bf16.bf16.f32 "
        "{%0,%1,%2,%3}, {%4,%5,%6,%7}, {%8,%9}, {%0,%1,%2,%3};"
        : "+f"(d[0]), "+f"(d[1]), "+f"(d[2]), "+f"(d[3])
        : "r"(a[0]), "r"(a[1]), "r"(a[2]), "r"(a[3]), "r"(b0), "r"(b1));
}
__device__ __forceinline__ void cp16(uint32_t dst, const void* src) {
    asm volatile("cp.async.cg.shared.global [%0], [%1], 16;" :: "r"(dst), "l"(src));
}
#define CP_COMMIT() asm volatile("cp.async.commit_group;" ::: "memory")
#define CP_WAIT0()  asm volatile("cp.async.wait_group 0;" ::: "memory")

// ================= bin + weight-prep (merged, independent work) ==============
__global__ void bin_prep_kernel(const int* __restrict__ ei,
                                const float* __restrict__ W1, const float* __restrict__ W2,
                                const float* __restrict__ W3, const float* __restrict__ W4) {
    int b = blockIdx.x;
    if (b < BIN_BLOCKS) {
        // --- slot binning: 4 edges per thread ---
        int t = b * 256 + threadIdx.x;
        int e0 = t * 4;
        if (e0 >= N_EDGES) return;
        int4 r = *reinterpret_cast<const int4*>(ei + e0);
        int4 c = *reinterpret_cast<const int4*>(ei + N_EDGES + e0);
        int p0 = atomicAdd(&g_cnt[r.x], 1);
        int p1 = atomicAdd(&g_cnt[r.y], 1);
        int p2 = atomicAdd(&g_cnt[r.z], 1);
        int p3 = atomicAdd(&g_cnt[r.w], 1);
        if (p0 < SLOTS) g_bcol[(size_t)r.x * SLOTS + p0] = c.x;
        if (p1 < SLOTS) g_bcol[(size_t)r.y * SLOTS + p1] = c.y;
        if (p2 < SLOTS) g_bcol[(size_t)r.z * SLOTS + p2] = c.z;
        if (p3 < SLOTS) g_bcol[(size_t)r.w * SLOTS + p3] = c.w;
    } else {
        // --- weight image prep ---
        int t = (b - BIN_BLOCKS) * 256 + threadIdx.x;
        if (t >= 57344) return;
        const float* W; int e, nout; uint32_t hoff, psz;
        if      (t < 16384) { e = t;         W = W1; nout = 128; hoff = 0;      psz = 32768; }
        else if (t < 32768) { e = t - 16384; W = W2; nout = 128; hoff = 65536;  psz = 32768; }
        else if (t < 49152) { e = t - 32768; W = W3; nout = 128; hoff = 131072; psz = 32768; }
        else                { e = t - 49152; W = W4; nout = 64;  hoff = 196608; psz = 16384; }
        int n = e >> 7;
        int k = e & 127;
        float w = W[k * nout + n];
        __nv_bfloat16 h = __float2bfloat16_rn(w);
        float res = w - __bfloat162float(h);
        __nv_bfloat16 l = __float2bfloat16_rn(res);
        uint32_t off = phys(n, k);
        *reinterpret_cast<__nv_bfloat16*>(g_wimg + hoff + off)       = h;
        *reinterpret_cast<__nv_bfloat16*>(g_wimg + hoff + psz + off) = l;
    }
}

// ---------------- fused gather + 4-layer MLP on HMMA ------------------------
#define SM_A_HI 0
#define SM_A_LO 16384
#define SM_W_HI 32768
#define SM_BIAS 98304
#define SM_TOTAL (98304 + 2048)     // 100352 bytes -> 2 CTAs/SM

template<int MT>
__device__ __forceinline__ void load_frags(
    uint32_t sb, uint32_t wlo, int kc,
    const uint32_t* arow_off, const int* ar7, int abit,
    const uint32_t* brow_off, const int* br7, int bbit,
    uint32_t ah[][4], uint32_t al[][4], uint32_t bh[][4], uint32_t bl[][4]) {
    #pragma unroll
    for (int mt = 0; mt < MT; mt++) {
        uint32_t off = arow_off[mt] + (uint32_t)((((kc << 1) + abit) ^ ar7[mt]) << 4);
        ldsm_x4(ah[mt], sb + SM_A_HI + off);
        ldsm_x4(al[mt], sb + SM_A_LO + off);
    }
    #pragma unroll
    for (int jp = 0; jp < 2; jp++) {
        uint32_t off = brow_off[jp] + (uint32_t)((((kc << 1) + bbit) ^ br7[jp]) << 4);
        ldsm_x4(bh[jp], sb + SM_W_HI + off);
        ldsm_x4(bl[jp], wlo + off);
    }
}

template<int NOUT, bool LAST>
__device__ __forceinline__ void layer_body(char* smem, uint32_t sb, float* __restrict__ out,
                                           int wid, int lane, int m0, const float* bl_s,
                                           uint32_t next_hoff, int next_f4, int tid) {
    constexpr int MT = (NOUT == 128) ? 2 : 1;
    const uint32_t wlo = sb + SM_W_HI + (uint32_t)NOUT * 256u;

    int warpM = (NOUT == 128) ? (wid >> 2) : (wid >> 1);
    int warpN = (NOUT == 128) ? (wid & 3) : (wid & 1);
    int mi    = lane >> 3;
    int lane8 = lane & 7;
    int g     = lane >> 2;
    int tt    = lane & 3;
    int nbase = warpN * 32;

    uint32_t arow_off[MT]; int ar7[MT]; int abit = mi >> 1;
    #pragma unroll
    for (int mt = 0; mt < MT; mt++) {
        int row = warpM * (MT * 16) + mt * 16 + (mi & 1) * 8 + lane8;
        arow_off[mt] = (uint32_t)row * 256u;
        ar7[mt] = row & 7;
    }
    uint32_t brow_off[2]; int br7[2]; int bbit = mi & 1;
    #pragma unroll
    for (int jp = 0; jp < 2; jp++) {
        int row = nbase + jp * 16 + (mi >> 1) * 8 + lane8;
        brow_off[jp] = (uint32_t)row * 256u;
        br7[jp] = row & 7;
    }

    float acc[MT][4][4];
    #pragma unroll
    for (int mt = 0; mt < MT; mt++)
        #pragma unroll
        for (int j = 0; j < 4; j++)
            #pragma unroll
            for (int q = 0; q < 4; q++) acc[mt][j][q] = 0.f;

    uint32_t ah[2][MT][4], al[2][MT][4], bh[2][2][4], bl[2][2][4];
    load_frags<MT>(sb, wlo, 0, arow_off, ar7, abit, brow_off, br7, bbit,
                   ah[0], al[0], bh[0], bl[0]);
    #pragma unroll
    for (int kc = 0; kc < 8; kc++) {
        int cur = kc & 1;
        if (kc < 7)
            load_frags<MT>(sb, wlo, kc + 1, arow_off, ar7, abit, brow_off, br7, bbit,
                           ah[cur ^ 1], al[cur ^ 1], bh[cur ^ 1], bl[cur ^ 1]);
        #pragma unroll
        for (int jp = 0; jp < 2; jp++)
            #pragma unroll
            for (int mt = 0; mt < MT; mt++) {
                mma_bf16(acc[mt][jp * 2],     ah[cur][mt], bh[cur][jp][0], bh[cur][jp][1]);
                mma_bf16(acc[mt][jp * 2 + 1], ah[cur][mt], bh[cur][jp][2], bh[cur][jp][3]);
            }
        #pragma unroll
        for (int jp = 0; jp < 2; jp++)
            #pragma unroll
            for (int mt = 0; mt < MT; mt++) {
                mma_bf16(acc[mt][jp * 2],     ah[cur][mt], bl[cur][jp][0], bl[cur][jp][1]);
                mma_bf16(acc[mt][jp * 2 + 1], ah[cur][mt], bl[cur][jp][2], bl[cur][jp][3]);
            }
        #pragma unroll
        for (int jp = 0; jp < 2; jp++)
            #pragma unroll
            for (int mt = 0; mt < MT; mt++) {
                mma_bf16(acc[mt][jp * 2],     al[cur][mt], bh[cur][jp][0], bh[cur][jp][1]);
                mma_bf16(acc[mt][jp * 2 + 1], al[cur][mt], bh[cur][jp][2], bh[cur][jp][3]);
            }
    }
    __syncthreads();

    if (!LAST) {
        const char* src = reinterpret_cast<const char*>(g_wimg + next_hoff);
        uint32_t dst = sb + SM_W_HI;
        for (int i = tid; i < next_f4; i += 256)
            cp16(dst + (uint32_t)i * 16u, src + (size_t)i * 16);
        CP_COMMIT();
    }

    #pragma unroll
    for (int mt = 0; mt < MT; mt++) {
        int rg0 = warpM * (MT * 16) + mt * 16 + g;
        #pragma unroll
        for (int j = 0; j < 4; j++) {
            int c0 = nbase + j * 8 + tt * 2;
            float bv0 = bl_s[c0], bv1 = bl_s[c0 + 1];
            float* d = acc[mt][j];
            if (!LAST) {
                float f0 = fmaxf(d[0] + bv0, 0.f), f1 = fmaxf(d[1] + bv1, 0.f);
                float f2 = fmaxf(d[2] + bv0, 0.f), f3 = fmaxf(d[3] + bv1, 0.f);
                __nv_bfloat16 h0 = __float2bfloat16_rn(f0), h1 = __float2bfloat16_rn(f1);
                __nv_bfloat16 h2 = __float2bfloat16_rn(f2), h3 = __float2bfloat16_rn(f3);
                uint32_t o0 = phys(rg0, c0);
                uint32_t o1 = phys(rg0 + 8, c0);
                *reinterpret_cast<uint32_t*>(smem + SM_A_HI + o0) =
                    bf2pack(__bfloat162float(h0), __bfloat162float(h1));
                *reinterpret_cast<uint32_t*>(smem + SM_A_LO + o0) =
                    bf2pack(f0 - __bfloat162float(h0), f1 - __bfloat162float(h1));
                *reinterpret_cast<uint32_t*>(smem + SM_A_HI + o1) =
                    bf2pack(__bfloat162float(h2), __bfloat162float(h3));
                *reinterpret_cast<uint32_t*>(smem + SM_A_LO + o1) =
                    bf2pack(f2 - __bfloat162float(h2), f3 - __bfloat162float(h3));
            } else {
                int node0 = m0 + rg0;
                int node1 = node0 + 8;
                if (node0 < N_NODES)
                    *reinterpret_cast<float2*>(out + (size_t)node0 * OUT_DIM + c0) =
                        make_float2(d[0] + bv0, d[1] + bv1);
                if (node1 < N_NODES)
                    *reinterpret_cast<float2*>(out + (size_t)node1 * OUT_DIM + c0) =
                        make_float2(d[2] + bv0, d[3] + bv1);
            }
        }
    }
    if (!LAST) CP_WAIT0();
    __syncthreads();
}

__global__ void __launch_bounds__(256, 2)
fused_mlp(const float* __restrict__ x,
          const float* __restrict__ b1, const float* __restrict__ b2,
          const float* __restrict__ b3, const float* __restrict__ b4,
          float* __restrict__ out) {
    extern __shared__ char smem[];
    uint32_t sb = smem_u32(smem);
    int tid = threadIdx.x, wid = tid >> 5, lane = tid & 31;
    int m0 = blockIdx.x * 64;

    float* bias_s = reinterpret_cast<float*>(smem + SM_BIAS);

    // layer-0 weights via cp.async, overlapping gather + A fill
    {
        const char* src = reinterpret_cast<const char*>(g_wimg);
        uint32_t dst = sb + SM_W_HI;
        for (int i = tid; i < 4096; i += 256)
            cp16(dst + (uint32_t)i * 16u, src + (size_t)i * 16);
        CP_COMMIT();
    }

    // ---- A fill with in-kernel slot-table gather: 4 threads per row ----
    // (round-15 proven form: each thread owns 4 contiguous float4 columns)
    {
        int row = tid >> 2;
        int sub = tid & 3;                 // 4 float4-columns each
        int node = m0 + row;
        int nsafe = node < N_NODES ? node : 0;

        const float4* xs = reinterpret_cast<const float4*>(x) + (size_t)nsafe * 16 + sub * 4;
        float4 xv[4];
        #pragma unroll
        for (int i = 0; i < 4; i++)
            xv[i] = (node < N_NODES) ? xs[i] : make_float4(0.f, 0.f, 0.f, 0.f);

        float4 acc[4];
        #pragma unroll
        for (int i = 0; i < 4; i++) acc[i] = make_float4(0.f, 0.f, 0.f, 0.f);
        if (node < N_NODES) {
            int cnt = g_cnt[node];
            int d   = cnt > 0 ? cnt : 1;
            int lim = cnt < SLOTS ? cnt : SLOTS;
            const int* bc = g_bcol + (size_t)node * SLOTS;
            for (int e = 0; e < lim; e++) {
                int cn = bc[e];
                const float4* xr = reinterpret_cast<const float4*>(x) + (size_t)cn * 16 + sub * 4;
                #pragma unroll
                for (int i = 0; i < 4; i++) {
                    float4 v = xr[i];
                    acc[i].x += v.x; acc[i].y += v.y; acc[i].z += v.z; acc[i].w += v.w;
                }
            }
            float inv = 1.0f / (float)d;
            #pragma unroll
            for (int i = 0; i < 4; i++) {
                acc[i].x *= inv; acc[i].y *= inv; acc[i].z *= inv; acc[i].w *= inv;
            }
        }

        #pragma unroll
        for (int half = 0; half < 2; half++) {
            #pragma unroll
            for (int i = 0; i < 4; i++) {
                float4 v = half ? acc[i] : xv[i];
                __nv_bfloat16 h0 = __float2bfloat16_rn(v.x), h1 = __float2bfloat16_rn(v.y);
                __nv_bfloat16 h2 = __float2bfloat16_rn(v.z), h3 = __float2bfloat16_rn(v.w);
                float r0 = v.x - __bfloat162float(h0), r1 = v.y - __bfloat162float(h1);
                float r2 = v.z - __bfloat162float(h2), r3 = v.w - __bfloat162float(h3);
                int c = half * 64 + (sub * 4 + i) * 4;
                uint32_t off = phys(row, c);
                ull hv = (ull)bf2pack(__bfloat162float(h0), __bfloat162float(h1))
                       | ((ull)bf2pack(__bfloat162float(h2), __bfloat162float(h3)) << 32);
                ull lv = (ull)bf2pack(r0, r1) | ((ull)bf2pack(r2, r3) << 32);
                *reinterpret_cast<ull*>(smem + SM_A_HI + off) = hv;
                *reinterpret_cast<ull*>(smem + SM_A_LO + off) = lv;
            }
        }
        if (tid < 128) {
            bias_s[tid]       = b1[tid];
            bias_s[128 + tid] = b2[tid];
            bias_s[256 + tid] = b3[tid];
            bias_s[384 + tid] = (tid < 64) ? b4[tid] : 0.f;
        }
    }
    CP_WAIT0();
    __syncthreads();

    layer_body<128, false>(smem, sb, out, wid, lane, m0, bias_s,       65536, 4096, tid);
    layer_body<128, false>(smem, sb, out, wid, lane, m0, bias_s + 128, 131072, 4096, tid);
    layer_body<128, false>(smem, sb, out, wid, lane, m0, bias_s + 256, 196608, 2048, tid);
    layer_body<64,  true >(smem, sb, out, wid, lane, m0, bias_s + 384, 0, 0, tid);
}

// ---------------- launch ----------------------------------------------------
extern "C" void kernel_launch(void* const* d_in, const int* in_sizes, int n_in,
                              void* d_out, int out_size) {
    const float* x  = (const float*)d_in[0];
    const int*   ei = (const int*)  d_in[1];
    const float* W1 = (const float*)d_in[2];
    const float* b1 = (const float*)d_in[3];
    const float* W2 = (const float*)d_in[4];
    const float* b2 = (const float*)d_in[5];
    const float* W3 = (const float*)d_in[6];
    const float* b3 = (const float*)d_in[7];
    const float* W4 = (const float*)d_in[8];
    const float* b4 = (const float*)d_in[9];
    float* out = (float*)d_out;

    cudaFuncSetAttribute(fused_mlp, cudaFuncAttributeMaxDynamicSharedMemorySize, SM_TOTAL);

    // zero per-node counters (graph-capturable async memset)
    void* cnt_ptr = nullptr;
    cudaGetSymbolAddress(&cnt_ptr, g_cnt);
    cudaMemsetAsync(cnt_ptr, 0, N_NODES * sizeof(int));

    // merged slot-binning + weight prep
    bin_prep_kernel<<<BIN_BLOCKS + PREP_BLOCKS, 256>>>(ei, W1, W2, W3, W4);
    // fused gather + 4-layer MLP
    int gblocks = (N_NODES + 63) / 64;   // 1563
    fused_mlp<<<gblocks, 256, SM_TOTAL>>>(x, b1, b2, b3, b4, out);
}